// round 2
// baseline (speedup 1.0000x reference)
#include <cuda_runtime.h>

// SNNReadout: out[t,b,c] = LIF-scan over t of (2 * sum_f spike[t,b,f]*mask[t,b,f]*W[c,f] + b[c])
// T=100, B=128, F=4096, C=10. HBM-bound: 420 MB streaming input reads.

#define T_STEPS 100
#define BATCH   128
#define FDIM    4096
#define CDIM    10
#define MROWS   (T_STEPS * BATCH)   // 12800 rows of the [M,F]x[F,C] GEMM
#define FC      1024                // K-chunk staged in smem
#define NCHUNK  (FDIM / FC)         // 4
#define RPW     4                   // rows per warp
#define NWARPS  8
#define ROWS_PER_BLOCK (RPW * NWARPS)  // 32

// 512 KB scratch for pre-activation currents (device global: no allocation allowed)
__device__ float g_current[MROWS * CDIM];

__global__ __launch_bounds__(256, 2)
void snn_gemm_kernel(const float* __restrict__ spk,
                     const float* __restrict__ msk,
                     const float* __restrict__ W,
                     const float* __restrict__ bias) {
    __shared__ float sW[CDIM * FC];   // 40 KB

    const int tid  = threadIdx.x;
    const int warp = tid >> 5;
    const int lane = tid & 31;
    const int row0 = blockIdx.x * ROWS_PER_BLOCK + warp * RPW;

    float acc[RPW][CDIM];
    #pragma unroll
    for (int r = 0; r < RPW; ++r)
        #pragma unroll
        for (int c = 0; c < CDIM; ++c)
            acc[r][c] = 0.0f;

    for (int ch = 0; ch < NCHUNK; ++ch) {
        __syncthreads();   // protect previous chunk's smem from overwrite
        // Cooperative load of W[:, ch*FC : (ch+1)*FC] into smem (float4, coalesced per c-slab)
        #pragma unroll 4
        for (int i = tid; i < CDIM * (FC / 4); i += 256) {
            const int c = i / (FC / 4);
            const int j = i % (FC / 4);
            float4 w = __ldg((const float4*)(W + (size_t)c * FDIM + (size_t)ch * FC) + j);
            ((float4*)sW)[c * (FC / 4) + j] = w;
        }
        __syncthreads();

        for (int q = 0; q < FC / 128; ++q) {      // each lane owns a float4 per 128-wide slice
            const int    fl = q * 128 + lane * 4; // f offset within chunk
            const size_t fg = (size_t)ch * FC + fl;

            // Batch all streaming loads first (8 independent LDG.128 -> MLP)
            float4 s4[RPW], m4[RPW];
            #pragma unroll
            for (int r = 0; r < RPW; ++r) {
                const size_t off = (size_t)(row0 + r) * FDIM + fg;
                s4[r] = __ldcs((const float4*)(spk + off));
                m4[r] = __ldcs((const float4*)(msk + off));
            }
            float4 x[RPW];
            #pragma unroll
            for (int r = 0; r < RPW; ++r) {
                x[r].x = s4[r].x * m4[r].x;
                x[r].y = s4[r].y * m4[r].y;
                x[r].z = s4[r].z * m4[r].z;
                x[r].w = s4[r].w * m4[r].w;
            }
            #pragma unroll
            for (int c = 0; c < CDIM; ++c) {
                const float4 w = *((const float4*)(sW + c * FC + fl));  // LDS.128, conflict-free
                #pragma unroll
                for (int r = 0; r < RPW; ++r) {
                    acc[r][c] = fmaf(x[r].x, w.x, acc[r][c]);
                    acc[r][c] = fmaf(x[r].y, w.y, acc[r][c]);
                    acc[r][c] = fmaf(x[r].z, w.z, acc[r][c]);
                    acc[r][c] = fmaf(x[r].w, w.w, acc[r][c]);
                }
            }
        }
    }

    // Warp reduction: each (r,c) partial summed across 32 lanes; lane c keeps value c.
    #pragma unroll
    for (int r = 0; r < RPW; ++r) {
        float outv = 0.0f;
        #pragma unroll
        for (int c = 0; c < CDIM; ++c) {
            float v = acc[r][c];
            #pragma unroll
            for (int off = 16; off > 0; off >>= 1)
                v += __shfl_xor_sync(0xFFFFFFFFu, v, off);
            if (lane == c) outv = v;
        }
        if (lane < CDIM) {
            // current = 2*sum + b  (x2 is an exact fp scaling; add matches reference rounding)
            g_current[(size_t)(row0 + r) * CDIM + lane] = 2.0f * outv + bias[lane];
        }
    }
}

// LIF scan: 1280 independent (b,c) chains over T=100. g_current is L2-hot (512 KB).
__global__ void snn_scan_kernel(float* __restrict__ out) {
    const int idx = blockIdx.x * blockDim.x + threadIdx.x;
    if (idx >= BATCH * CDIM) return;

    float v = 0.0f;
    #pragma unroll 4
    for (int t = 0; t < T_STEPS; ++t) {
        const float cur = g_current[t * (BATCH * CDIM) + idx];
        v = fmaf(v, 0.9f, cur);              // v*BETA + current, BETA = 1 - 1/10
        const float s = (v > 1.0f) ? 1.0f : 0.0f;  // atan_spike fwd: (v - V_TH) > 0
        out[t * (BATCH * CDIM) + idx] = s;
        v -= s;                              // soft reset, V_TH = 1
    }
}

extern "C" void kernel_launch(void* const* d_in, const int* in_sizes, int n_in,
                              void* d_out, int out_size) {
    const float* spk  = (const float*)d_in[0];  // spike_seq [T,B,F]
    const float* msk  = (const float*)d_in[1];  // drop_mask [T,B,F]
    const float* W    = (const float*)d_in[2];  // W [C,F]
    const float* bias = (const float*)d_in[3];  // b [C]
    float* out = (float*)d_out;                 // out_spikes [T,B,C] fp32

    snn_gemm_kernel<<<MROWS / ROWS_PER_BLOCK, 256>>>(spk, msk, W, bias);
    snn_scan_kernel<<<(BATCH * CDIM + 127) / 128, 128>>>(out);
}

// round 5
// speedup vs baseline: 1.2723x; 1.2723x over previous
#include <cuda_runtime.h>

// SNNReadout: out[t,b,c] = LIF-scan over t of (2 * sum_f spike[t,b,f]*mask[t,b,f]*W[c,f] + b[c])
// T=100, B=128, F=4096, C=10. HBM-bound: 420 MB streaming reads. fp32 exactness
// required by the Heaviside threshold -> no tensor cores; use packed f32x2 FMA.

#define T_STEPS 100
#define BATCH   128
#define FDIM    4096
#define CDIM    10
#define MROWS   (T_STEPS * BATCH)      // 12800
#define FC      1024                   // K-chunk staged in smem (40 KB)
#define NCHUNK  (FDIM / FC)            // 4
#define RPW     2                      // rows per warp (pairs well with f32x2 f-packing)
#define NWARPS  8
#define ROWS_PER_BLOCK (RPW * NWARPS)  // 16 -> 800 blocks (2.7 waves @occ2, ~90% eff)

typedef unsigned long long u64;

__device__ float g_current[MROWS * CDIM];   // 512 KB scratch (no allocation allowed)

__device__ __forceinline__ u64 mul2(u64 a, u64 b) {
    u64 d; asm("mul.rn.f32x2 %0, %1, %2;" : "=l"(d) : "l"(a), "l"(b)); return d;
}
__device__ __forceinline__ u64 fma2(u64 a, u64 b, u64 c) {
    u64 d; asm("fma.rn.f32x2 %0, %1, %2, %3;" : "=l"(d) : "l"(a), "l"(b), "l"(c)); return d;
}
__device__ __forceinline__ ulonglong2 ldcs128(const float* p) {
    ulonglong2 r;
    asm("ld.global.cs.v2.b64 {%0, %1}, [%2];" : "=l"(r.x), "=l"(r.y) : "l"(p));
    return r;
}
__device__ __forceinline__ float sum2(u64 a) {
    float lo, hi;
    asm("mov.b64 {%0, %1}, %2;" : "=f"(lo), "=f"(hi) : "l"(a));
    return lo + hi;
}

__global__ __launch_bounds__(256, 2)
void snn_gemm_kernel(const float* __restrict__ spk,
                     const float* __restrict__ msk,
                     const float* __restrict__ W,
                     const float* __restrict__ bias) {
    __shared__ float sW[CDIM * FC];   // 40 KB

    const int tid  = threadIdx.x;
    const int warp = tid >> 5;
    const int lane = tid & 31;
    const int row0 = blockIdx.x * ROWS_PER_BLOCK + warp * RPW;

    u64 acc[RPW][CDIM];               // packed f32x2: lo sums even-of-pair f, hi odd
    #pragma unroll
    for (int r = 0; r < RPW; ++r)
        #pragma unroll
        for (int c = 0; c < CDIM; ++c)
            acc[r][c] = 0ULL;

    for (int ch = 0; ch < NCHUNK; ++ch) {
        __syncthreads();              // protect previous chunk's smem
        #pragma unroll 4
        for (int i = tid; i < CDIM * (FC / 4); i += 256) {
            const int c = i / (FC / 4);
            const int j = i % (FC / 4);
            float4 w = __ldg((const float4*)(W + (size_t)c * FDIM + (size_t)ch * FC) + j);
            ((float4*)sW)[c * (FC / 4) + j] = w;
        }
        __syncthreads();

        const float* sp0 = spk + (size_t)row0 * FDIM + (size_t)ch * FC;
        const float* sp1 = sp0 + FDIM;
        const float* mp0 = msk + (size_t)row0 * FDIM + (size_t)ch * FC;
        const float* mp1 = mp0 + FDIM;

        #pragma unroll
        for (int q = 0; q < FC / 128; q += 2) {
            const int fl0 = q * 128 + lane * 4;

            // Batch 8 independent LDG.128 (two q-slices x two rows x {spk,msk})
            ulonglong2 s[2][2], m[2][2];
            #pragma unroll
            for (int u = 0; u < 2; ++u) {
                const int fl = fl0 + u * 128;
                s[u][0] = ldcs128(sp0 + fl);
                m[u][0] = ldcs128(mp0 + fl);
                s[u][1] = ldcs128(sp1 + fl);
                m[u][1] = ldcs128(mp1 + fl);
            }

            #pragma unroll
            for (int u = 0; u < 2; ++u) {
                const int fl = fl0 + u * 128;
                u64 x[RPW][2];
                #pragma unroll
                for (int r = 0; r < RPW; ++r) {
                    x[r][0] = mul2(s[u][r].x, m[u][r].x);
                    x[r][1] = mul2(s[u][r].y, m[u][r].y);
                }
                #pragma unroll
                for (int c = 0; c < CDIM; ++c) {
                    const ulonglong2 w = *((const ulonglong2*)(sW + c * FC + fl)); // LDS.128
                    #pragma unroll
                    for (int r = 0; r < RPW; ++r) {
                        acc[r][c] = fma2(x[r][0], w.x, acc[r][c]);
                        acc[r][c] = fma2(x[r][1], w.y, acc[r][c]);
                    }
                }
            }
        }
    }

    // Reduce: lo+hi of each packed acc, then across 32 lanes; lane c keeps class c.
    #pragma unroll
    for (int r = 0; r < RPW; ++r) {
        float outv = 0.0f;
        #pragma unroll
        for (int c = 0; c < CDIM; ++c) {
            float v = sum2(acc[r][c]);
            #pragma unroll
            for (int off = 16; off > 0; off >>= 1)
                v += __shfl_xor_sync(0xFFFFFFFFu, v, off);
            if (lane == c) outv = v;
        }
        if (lane < CDIM)
            g_current[(size_t)(row0 + r) * CDIM + lane] = 2.0f * outv + bias[lane];
    }
}

// LIF scan: 1280 independent chains over T=100. Preload all currents into a
// statically-indexed register array (one MLP burst), then pure ALU chain.
__global__ __launch_bounds__(32)
void snn_scan_kernel(float* __restrict__ out) {
    const int idx = blockIdx.x * 32 + threadIdx.x;   // 40 blocks x 32 = 1280 chains

    float cur[T_STEPS];
    #pragma unroll
    for (int t = 0; t < T_STEPS; ++t)
        cur[t] = g_current[t * (BATCH * CDIM) + idx];

    float v = 0.0f;
    #pragma unroll
    for (int t = 0; t < T_STEPS; ++t) {
        v = fmaf(v, 0.9f, cur[t]);                   // v*BETA + current
        const float s = (v > 1.0f) ? 1.0f : 0.0f;    // Heaviside(v - V_TH)
        out[t * (BATCH * CDIM) + idx] = s;
        v -= s;                                      // soft reset
    }
}

extern "C" void kernel_launch(void* const* d_in, const int* in_sizes, int n_in,
                              void* d_out, int out_size) {
    const float* spk  = (const float*)d_in[0];  // spike_seq [T,B,F]
    const float* msk  = (const float*)d_in[1];  // drop_mask [T,B,F]
    const float* W    = (const float*)d_in[2];  // W [C,F]
    const float* bias = (const float*)d_in[3];  // b [C]
    float* out = (float*)d_out;                 // out_spikes [T,B,C] fp32

    snn_gemm_kernel<<<MROWS / ROWS_PER_BLOCK, 256>>>(spk, msk, W, bias);
    snn_scan_kernel<<<(BATCH * CDIM) / 32, 32>>>(out);
}

// round 7
// speedup vs baseline: 1.3057x; 1.0263x over previous
#include <cuda_runtime.h>

// SNNReadout: out[t,b,c] = LIF-scan over t of (2 * sum_f spike[t,b,f]*mask[t,b,f]*W[c,f] + b[c])
// T=100, B=128, F=4096, C=10. HBM-bound: 420 MB streaming reads. fp32 exactness
// required by the Heaviside threshold -> no tensor cores; use packed f32x2 FMA.

#define T_STEPS 100
#define BATCH   128
#define FDIM    4096
#define CDIM    10
#define MROWS   (T_STEPS * BATCH)      // 12800
#define FC      1024                   // K-chunk staged in smem (40 KB)
#define NCHUNK  (FDIM / FC)            // 4
#define RPW     2                      // rows per warp (pairs well with f32x2 f-packing)
#define NWARPS  8
#define ROWS_PER_BLOCK (RPW * NWARPS)  // 16 -> 800 blocks (2.7 waves @occ2, ~90% eff)

#define NCHAINS (BATCH * CDIM)         // 1280
#define SCAN_CPB 64                    // chains per scan block -> 20 blocks, 25.6 KB smem

typedef unsigned long long u64;

__device__ float g_current[MROWS * CDIM];   // 512 KB scratch (no allocation allowed)

__device__ __forceinline__ u64 mul2(u64 a, u64 b) {
    u64 d; asm("mul.rn.f32x2 %0, %1, %2;" : "=l"(d) : "l"(a), "l"(b)); return d;
}
__device__ __forceinline__ u64 fma2(u64 a, u64 b, u64 c) {
    u64 d; asm("fma.rn.f32x2 %0, %1, %2, %3;" : "=l"(d) : "l"(a), "l"(b), "l"(c)); return d;
}
__device__ __forceinline__ ulonglong2 ldcs128(const float* p) {
    ulonglong2 r;
    asm("ld.global.cs.v2.b64 {%0, %1}, [%2];" : "=l"(r.x), "=l"(r.y) : "l"(p));
    return r;
}
__device__ __forceinline__ float sum2(u64 a) {
    float lo, hi;
    asm("mov.b64 {%0, %1}, %2;" : "=f"(lo), "=f"(hi) : "l"(a));
    return lo + hi;
}

__global__ __launch_bounds__(256, 2)
void snn_gemm_kernel(const float* __restrict__ spk,
                     const float* __restrict__ msk,
                     const float* __restrict__ W,
                     const float* __restrict__ bias) {
    __shared__ float sW[CDIM * FC];   // 40 KB

    const int tid  = threadIdx.x;
    const int warp = tid >> 5;
    const int lane = tid & 31;
    const int row0 = blockIdx.x * ROWS_PER_BLOCK + warp * RPW;

    u64 acc[RPW][CDIM];               // packed f32x2: lo sums even-of-pair f, hi odd
    #pragma unroll
    for (int r = 0; r < RPW; ++r)
        #pragma unroll
        for (int c = 0; c < CDIM; ++c)
            acc[r][c] = 0ULL;

    for (int ch = 0; ch < NCHUNK; ++ch) {
        __syncthreads();              // protect previous chunk's smem
        #pragma unroll 4
        for (int i = tid; i < CDIM * (FC / 4); i += 256) {
            const int c = i / (FC / 4);
            const int j = i % (FC / 4);
            float4 w = __ldg((const float4*)(W + (size_t)c * FDIM + (size_t)ch * FC) + j);
            ((float4*)sW)[c * (FC / 4) + j] = w;
        }
        __syncthreads();

        const float* sp0 = spk + (size_t)row0 * FDIM + (size_t)ch * FC;
        const float* sp1 = sp0 + FDIM;
        const float* mp0 = msk + (size_t)row0 * FDIM + (size_t)ch * FC;
        const float* mp1 = mp0 + FDIM;

        #pragma unroll
        for (int q = 0; q < FC / 128; q += 2) {
            const int fl0 = q * 128 + lane * 4;

            // Batch 8 independent LDG.128 (two q-slices x two rows x {spk,msk})
            ulonglong2 s[2][2], m[2][2];
            #pragma unroll
            for (int u = 0; u < 2; ++u) {
                const int fl = fl0 + u * 128;
                s[u][0] = ldcs128(sp0 + fl);
                m[u][0] = ldcs128(mp0 + fl);
                s[u][1] = ldcs128(sp1 + fl);
                m[u][1] = ldcs128(mp1 + fl);
            }

            #pragma unroll
            for (int u = 0; u < 2; ++u) {
                const int fl = fl0 + u * 128;
                u64 x[RPW][2];
                #pragma unroll
                for (int r = 0; r < RPW; ++r) {
                    x[r][0] = mul2(s[u][r].x, m[u][r].x);
                    x[r][1] = mul2(s[u][r].y, m[u][r].y);
                }
                #pragma unroll
                for (int c = 0; c < CDIM; ++c) {
                    const ulonglong2 w = *((const ulonglong2*)(sW + c * FC + fl)); // LDS.128
                    #pragma unroll
                    for (int r = 0; r < RPW; ++r) {
                        acc[r][c] = fma2(x[r][0], w.x, acc[r][c]);
                        acc[r][c] = fma2(x[r][1], w.y, acc[r][c]);
                    }
                }
            }
        }
    }

    // Reduce: lo+hi of each packed acc, then across 32 lanes; lane c keeps class c.
    #pragma unroll
    for (int r = 0; r < RPW; ++r) {
        float outv = 0.0f;
        #pragma unroll
        for (int c = 0; c < CDIM; ++c) {
            float v = sum2(acc[r][c]);
            #pragma unroll
            for (int off = 16; off > 0; off >>= 1)
                v += __shfl_xor_sync(0xFFFFFFFFu, v, off);
            if (lane == c) outv = v;
        }
        if (lane < CDIM)
            g_current[(size_t)(row0 + r) * CDIM + lane] = 2.0f * outv + bias[lane];
    }
}

// LIF scan: 1280 independent chains over T=100. Stage each block's 64 chains x
// 100 steps in smem via one bulk MLP load burst (no chain dependency), then run
// the pure ALU dependent chain out of smem. Registers stay small (no spill).
__global__ __launch_bounds__(SCAN_CPB)
void snn_scan_kernel(float* __restrict__ out) {
    __shared__ float scur[T_STEPS * SCAN_CPB];       // 25.6 KB

    const int tid  = threadIdx.x;
    const int base = blockIdx.x * SCAN_CPB;          // first chain of this block

    // Bulk load: 100 t-rows x 16 float4 per block = 1600 independent LDG.128.
    const float4* gc4 = (const float4*)g_current;
    #pragma unroll 8
    for (int i = tid; i < T_STEPS * (SCAN_CPB / 4); i += SCAN_CPB) {
        const int t = i / (SCAN_CPB / 4);
        const int j = i % (SCAN_CPB / 4);
        ((float4*)scur)[t * (SCAN_CPB / 4) + j] =
            gc4[(t * NCHAINS + base) / 4 + j];
    }
    __syncthreads();

    float v = 0.0f;
    #pragma unroll
    for (int t = 0; t < T_STEPS; ++t) {
        const float cur = scur[t * SCAN_CPB + tid];  // conflict-free LDS, prefetchable
        v = fmaf(v, 0.9f, cur);                      // v*BETA + current
        const float s = (v > 1.0f) ? 1.0f : 0.0f;    // Heaviside(v - V_TH)
        out[t * NCHAINS + base + tid] = s;
        v -= s;                                      // soft reset
    }
}

extern "C" void kernel_launch(void* const* d_in, const int* in_sizes, int n_in,
                              void* d_out, int out_size) {
    const float* spk  = (const float*)d_in[0];  // spike_seq [T,B,F]
    const float* msk  = (const float*)d_in[1];  // drop_mask [T,B,F]
    const float* W    = (const float*)d_in[2];  // W [C,F]
    const float* bias = (const float*)d_in[3];  // b [C]
    float* out = (float*)d_out;                 // out_spikes [T,B,C] fp32

    snn_gemm_kernel<<<MROWS / ROWS_PER_BLOCK, 256>>>(spk, msk, W, bias);
    snn_scan_kernel<<<NCHAINS / SCAN_CPB, SCAN_CPB>>>(out);
}

// round 9
// speedup vs baseline: 1.3089x; 1.0024x over previous
#include <cuda_runtime.h>

// SNNReadout: out[t,b,c] = LIF-scan over t of (2 * sum_f spike[t,b,f]*mask[t,b,f]*W[c,f] + b[c])
// T=100, B=128, F=4096, C=10. HBM-bound: 420 MB streaming reads. fp32 exactness
// required by the Heaviside threshold -> no tensor cores; packed f32x2 FMA.
//
// GEMM design: W (160 KB) fully resident in dynamic smem, one 512-thread block
// per SM (grid=152 = exactly one wave, no tail), per-warp contiguous balanced
// row ranges, rows processed in pairs to amortize W LDS.128 across 2 rows.

#define T_STEPS 100
#define BATCH   128
#define FDIM    4096
#define CDIM    10
#define MROWS   (T_STEPS * BATCH)      // 12800
#define NCHAINS (BATCH * CDIM)         // 1280
#define SCAN_CPB 64                    // chains per scan block -> 20 blocks

#define GEMM_GRID 152                  // GB300: 152 SMs, occ 1 -> one exact wave
#define GEMM_TPB  512
#define WARPS_TOT (GEMM_GRID * (GEMM_TPB / 32))   // 2432
#define SW_BYTES  (CDIM * FDIM * 4)    // 160 KB

typedef unsigned long long u64;

__device__ float g_current[MROWS * CDIM];   // 512 KB scratch (no allocation allowed)

__device__ __forceinline__ u64 mul2(u64 a, u64 b) {
    u64 d; asm("mul.rn.f32x2 %0, %1, %2;" : "=l"(d) : "l"(a), "l"(b)); return d;
}
__device__ __forceinline__ u64 fma2(u64 a, u64 b, u64 c) {
    u64 d; asm("fma.rn.f32x2 %0, %1, %2, %3;" : "=l"(d) : "l"(a), "l"(b), "l"(c)); return d;
}
__device__ __forceinline__ ulonglong2 ldcs128(const float* p) {
    ulonglong2 r;
    asm("ld.global.cs.v2.b64 {%0, %1}, [%2];" : "=l"(r.x), "=l"(r.y) : "l"(p));
    return r;
}
__device__ __forceinline__ float sum2(u64 a) {
    float lo, hi;
    asm("mov.b64 {%0, %1}, %2;" : "=f"(lo), "=f"(hi) : "l"(a));
    return lo + hi;
}

__device__ __forceinline__ float warp_red_keep(float v, int lane, int c, float cur) {
    #pragma unroll
    for (int off = 16; off > 0; off >>= 1)
        v += __shfl_xor_sync(0xFFFFFFFFu, v, off);
    return (lane == c) ? v : cur;
}

__global__ __launch_bounds__(GEMM_TPB, 1)
void snn_gemm_kernel(const float* __restrict__ spk,
                     const float* __restrict__ msk,
                     const float* __restrict__ W,
                     const float* __restrict__ bias) {
    extern __shared__ float sW[];      // 160 KB: full W[c][f]

    const int tid  = threadIdx.x;
    const int warp = tid >> 5;
    const int lane = tid & 31;

    // Stage full W once (L2-hit after first block; 160 KB)
    for (int i = tid; i < CDIM * FDIM / 4; i += GEMM_TPB)
        ((float4*)sW)[i] = __ldg((const float4*)W + i);
    __syncthreads();

    const float bv = (lane < CDIM) ? __ldg(bias + lane) : 0.0f;

    // Balanced contiguous row range for this warp (5 or 6 rows)
    const int gw   = blockIdx.x * (GEMM_TPB / 32) + warp;
    int       row  = (int)((long long)gw * MROWS / WARPS_TOT);
    const int rend = (int)((long long)(gw + 1) * MROWS / WARPS_TOT);

    // ---- row pairs: share each W LDS.128 across 2 rows ----
    for (; row + 2 <= rend; row += 2) {
        const float* sp0 = spk + (size_t)row * FDIM;
        const float* mp0 = msk + (size_t)row * FDIM;

        u64 acc[2][CDIM];
        #pragma unroll
        for (int r = 0; r < 2; ++r)
            #pragma unroll
            for (int c = 0; c < CDIM; ++c) acc[r][c] = 0ULL;

        #pragma unroll 1
        for (int q = 0; q < FDIM / 128; q += 2) {      // 2 q-slices per iter
            const int fl0 = q * 128 + lane * 4;

            ulonglong2 s[2][2], m[2][2];               // 8 independent LDG.128
            #pragma unroll
            for (int u = 0; u < 2; ++u) {
                const int fl = fl0 + u * 128;
                s[u][0] = ldcs128(sp0 + fl);
                m[u][0] = ldcs128(mp0 + fl);
                s[u][1] = ldcs128(sp0 + FDIM + fl);
                m[u][1] = ldcs128(mp0 + FDIM + fl);
            }
            #pragma unroll
            for (int u = 0; u < 2; ++u) {
                const int fl = fl0 + u * 128;
                u64 x[2][2];
                #pragma unroll
                for (int r = 0; r < 2; ++r) {
                    x[r][0] = mul2(s[u][r].x, m[u][r].x);
                    x[r][1] = mul2(s[u][r].y, m[u][r].y);
                }
                #pragma unroll
                for (int c = 0; c < CDIM; ++c) {
                    const ulonglong2 w = *((const ulonglong2*)(sW + c * FDIM + fl));
                    #pragma unroll
                    for (int r = 0; r < 2; ++r) {
                        acc[r][c] = fma2(x[r][0], w.x, acc[r][c]);
                        acc[r][c] = fma2(x[r][1], w.y, acc[r][c]);
                    }
                }
            }
        }
        #pragma unroll
        for (int r = 0; r < 2; ++r) {
            float outv = 0.0f;
            #pragma unroll
            for (int c = 0; c < CDIM; ++c)
                outv = warp_red_keep(sum2(acc[r][c]), lane, c, outv);
            if (lane < CDIM)
                g_current[(size_t)(row + r) * CDIM + lane] = 2.0f * outv + bv;
        }
    }

    // ---- leftover single row ----
    if (row < rend) {
        const float* sp0 = spk + (size_t)row * FDIM;
        const float* mp0 = msk + (size_t)row * FDIM;

        u64 acc[CDIM];
        #pragma unroll
        for (int c = 0; c < CDIM; ++c) acc[c] = 0ULL;

        #pragma unroll 1
        for (int q = 0; q < FDIM / 128; q += 4) {      // 4 q-slices -> 8 LDG.128
            const int fl0 = q * 128 + lane * 4;
            ulonglong2 s[4], m[4];
            #pragma unroll
            for (int u = 0; u < 4; ++u) {
                s[u] = ldcs128(sp0 + fl0 + u * 128);
                m[u] = ldcs128(mp0 + fl0 + u * 128);
            }
            #pragma unroll
            for (int u = 0; u < 4; ++u) {
                const int fl = fl0 + u * 128;
                const u64 x0 = mul2(s[u].x, m[u].x);
                const u64 x1 = mul2(s[u].y, m[u].y);
                #pragma unroll
                for (int c = 0; c < CDIM; ++c) {
                    const ulonglong2 w = *((const ulonglong2*)(sW + c * FDIM + fl));
                    acc[c] = fma2(x0, w.x, acc[c]);
                    acc[c] = fma2(x1, w.y, acc[c]);
                }
            }
        }
        float outv = 0.0f;
        #pragma unroll
        for (int c = 0; c < CDIM; ++c)
            outv = warp_red_keep(sum2(acc[c]), lane, c, outv);
        if (lane < CDIM)
            g_current[(size_t)row * CDIM + lane] = 2.0f * outv + bv;
    }
}

// LIF scan: 256 threads cooperatively bulk-load 64 chains x 100 steps into smem
// (8 warps share the MLP burst), then 64 threads run the dependent ALU chain.
__global__ __launch_bounds__(256)
void snn_scan_kernel(float* __restrict__ out) {
    __shared__ float scur[T_STEPS * SCAN_CPB];       // 25.6 KB

    const int tid  = threadIdx.x;
    const int base = blockIdx.x * SCAN_CPB;

    const float4* gc4 = (const float4*)g_current;
    #pragma unroll 2
    for (int i = tid; i < T_STEPS * (SCAN_CPB / 4); i += 256) {
        const int t = i / (SCAN_CPB / 4);
        const int j = i % (SCAN_CPB / 4);
        ((float4*)scur)[i] = gc4[t * (NCHAINS / 4) + base / 4 + j];
    }
    __syncthreads();

    if (tid < SCAN_CPB) {
        float v = 0.0f;
        #pragma unroll
        for (int t = 0; t < T_STEPS; ++t) {
            const float cur = scur[t * SCAN_CPB + tid];
            v = fmaf(v, 0.9f, cur);                      // v*BETA + current
            const float s = (v > 1.0f) ? 1.0f : 0.0f;    // Heaviside(v - V_TH)
            out[t * NCHAINS + base + tid] = s;
            v -= s;                                      // soft reset
        }
    }
}

extern "C" void kernel_launch(void* const* d_in, const int* in_sizes, int n_in,
                              void* d_out, int out_size) {
    const float* spk  = (const float*)d_in[0];  // spike_seq [T,B,F]
    const float* msk  = (const float*)d_in[1];  // drop_mask [T,B,F]
    const float* W    = (const float*)d_in[2];  // W [C,F]
    const float* bias = (const float*)d_in[3];  // b [C]
    float* out = (float*)d_out;                 // out_spikes [T,B,C] fp32

    // Non-stream API: capture-safe; also runs on the uncaptured correctness call.
    cudaFuncSetAttribute(snn_gemm_kernel,
                         cudaFuncAttributeMaxDynamicSharedMemorySize, SW_BYTES);

    snn_gemm_kernel<<<GEMM_GRID, GEMM_TPB, SW_BYTES>>>(spk, msk, W, bias);
    snn_scan_kernel<<<NCHAINS / SCAN_CPB, 256>>>(out);
}